// round 11
// baseline (speedup 1.0000x reference)
#include <cuda_runtime.h>
#include <cuda_fp16.h>
#include <math.h>

#define B_   2
#define S_   4096
#define DM_  1024
#define H_   16
#define HD_  64
#define MROWS (B_ * S_)

__device__ __half g_q[MROWS * DM_];
__device__ __half g_k[MROWS * DM_];
__device__ __half g_v[MROWS * DM_];
__device__ __half g_attn[MROWS * DM_];
__device__ __half g_xh[MROWS * DM_];
__device__ __half g_wqt[DM_ * DM_];
__device__ __half g_wkt[DM_ * DM_];
__device__ __half g_wvt[DM_ * DM_];
__device__ __half g_wot[DM_ * DM_];

__device__ __forceinline__ void mma_f16(float c[4], const unsigned a[4],
                                        const unsigned b[2]) {
  asm volatile(
      "mma.sync.aligned.m16n8k16.row.col.f32.f16.f16.f32 "
      "{%0,%1,%2,%3}, {%4,%5,%6,%7}, {%8,%9}, {%0,%1,%2,%3};"
      : "+f"(c[0]), "+f"(c[1]), "+f"(c[2]), "+f"(c[3])
      : "r"(a[0]), "r"(a[1]), "r"(a[2]), "r"(a[3]), "r"(b[0]), "r"(b[1]));
}

__device__ __forceinline__ void ldsm4(unsigned r[4], const void* p) {
  unsigned a = (unsigned)__cvta_generic_to_shared(p);
  asm volatile(
      "ldmatrix.sync.aligned.m8n8.x4.shared.b16 {%0,%1,%2,%3}, [%4];"
      : "=r"(r[0]), "=r"(r[1]), "=r"(r[2]), "=r"(r[3])
      : "r"(a));
}

__device__ __forceinline__ void ldsm4t(unsigned r[4], const void* p) {
  unsigned a = (unsigned)__cvta_generic_to_shared(p);
  asm volatile(
      "ldmatrix.sync.aligned.m8n8.x4.trans.shared.b16 {%0,%1,%2,%3}, [%4];"
      : "=r"(r[0]), "=r"(r[1]), "=r"(r[2]), "=r"(r[3])
      : "r"(a));
}

// ---- bulk-copy (UBLKCP) + mbarrier staging ----
__device__ __forceinline__ void cpbulk(unsigned dst_smem, const void* gsrc,
                                       unsigned bytes, unsigned mbar) {
  asm volatile(
      "cp.async.bulk.shared::cluster.global.mbarrier::complete_tx::bytes "
      "[%0], [%1], %2, [%3];"
      ::"r"(dst_smem), "l"(gsrc), "r"(bytes), "r"(mbar) : "memory");
}
__device__ __forceinline__ void mbar_init(unsigned addr, unsigned cnt) {
  asm volatile("mbarrier.init.shared.b64 [%0], %1;" ::"r"(addr), "r"(cnt)
               : "memory");
}
__device__ __forceinline__ void mbar_expect(unsigned addr, unsigned bytes) {
  asm volatile("mbarrier.arrive.expect_tx.shared.b64 _, [%0], %1;"
               ::"r"(addr), "r"(bytes) : "memory");
}
__device__ __forceinline__ void mbar_wait(unsigned addr, unsigned parity) {
  asm volatile(
      "{\n\t.reg .pred P;\n\t"
      "WL%=:\n\t"
      "mbarrier.try_wait.parity.acquire.cta.shared::cta.b64 P, [%0], %1;\n\t"
      "@!P bra WL%=;\n\t}"
      ::"r"(addr), "r"(parity) : "memory");
}

__device__ __forceinline__ unsigned pack_h2(float lo, float hi) {
  __half2 h = __floats2half2_rn(lo, hi);
  return *(unsigned*)&h;
}

// ---------------------------------------------------------------------------
// Pre-pass: fp32 -> fp16 (x), and transpose + fp16 (weights).
// ---------------------------------------------------------------------------
__global__ void f2h_kernel(const float* __restrict__ in,
                           __half* __restrict__ out, long n4) {
  long i = (long)blockIdx.x * blockDim.x + threadIdx.x;
  long stride = (long)gridDim.x * blockDim.x;
  for (; i < n4; i += stride) {
    float4 v = ((const float4*)in)[i];
    ((__half2*)out)[2 * i]     = __floats2half2_rn(v.x, v.y);
    ((__half2*)out)[2 * i + 1] = __floats2half2_rn(v.z, v.w);
  }
}

__global__ __launch_bounds__(256) void f2hT_kernel(
    const float* __restrict__ in, __half* __restrict__ out) {
  __shared__ float t[32][33];
  int k0 = blockIdx.x * 32, n0 = blockIdx.y * 32;
  int tx = threadIdx.x & 31, ty = threadIdx.x >> 5;
#pragma unroll
  for (int i = 0; i < 32; i += 8)
    t[ty + i][tx] = in[(long)(k0 + ty + i) * DM_ + n0 + tx];
  __syncthreads();
#pragma unroll
  for (int i = 0; i < 32; i += 8)
    out[(long)(n0 + ty + i) * DM_ + k0 + tx] = __float2half_rn(t[tx][ty + i]);
}

// ---------------------------------------------------------------------------
// GEMM: C = A @ W + bias, A[M,K] half, Wt[n][k] half (pre-transposed).
// CTA 128x128, 4 warps x (64x64). K staged 64 via cp.async.bulk (one 128B
// bulk op per tile row per matrix: 2 ops/thread vs 16 LDGSTS) + mbarrier.
// ---------------------------------------------------------------------------
#define GST 9216  // halves per (matrix, stage): 128*72

template <int OUTH>
__device__ __forceinline__ void gemm_body_h(
    const __half* __restrict__ A, const __half* __restrict__ Wt,
    const float* __restrict__ bias, void* Cv, float oscale, long m0, int n0) {
  extern __shared__ __half gsm[];
  __half* As = gsm;             // [2][128*72]
  __half* Bs = gsm + 2 * GST;   // [2][128*72]
  __shared__ unsigned long long gmb[2];

  const int tid  = threadIdx.x;
  const int lane = tid & 31;
  const int wid  = tid >> 5;   // 0..3
  const int g    = lane >> 2;
  const int tg   = lane & 3;
  const int wm   = wid & 1;
  const int wn   = wid >> 1;
  const int lrow = lane & 7;
  const int koct = ((lane >> 3) & 1) << 3;
  const int hoct = (lane >> 4) << 3;

  unsigned mb0 = (unsigned)__cvta_generic_to_shared(&gmb[0]);
  unsigned mb1 = (unsigned)__cvta_generic_to_shared(&gmb[1]);
  unsigned asb = (unsigned)__cvta_generic_to_shared(As);
  unsigned bsb = (unsigned)__cvta_generic_to_shared(Bs);

  if (tid == 0) {
    mbar_init(mb0, 128);
    mbar_init(mb1, 128);
  }
  __syncthreads();

  // one A row + one B row (128B each) per thread per stage
  auto stage = [&](int k0, int buf) {
    unsigned mb = buf ? mb1 : mb0;
    mbar_expect(mb, 256);
    cpbulk(asb + buf * (GST * 2) + tid * 144,
           A + (m0 + tid) * DM_ + k0, 128, mb);
    cpbulk(bsb + buf * (GST * 2) + tid * 144,
           Wt + (long)(n0 + tid) * DM_ + k0, 128, mb);
  };

  float acc[4][8][4];
#pragma unroll
  for (int mt = 0; mt < 4; mt++)
#pragma unroll
    for (int nt = 0; nt < 8; nt++)
#pragma unroll
      for (int j = 0; j < 4; j++) acc[mt][nt][j] = 0.f;

  stage(0, 0);
  stage(64, 1);

  const int NT = DM_ / 64;  // 16
  for (int kt = 0; kt < NT; kt++) {
    const int buf = kt & 1;
    mbar_wait(buf ? mb1 : mb0, (kt >> 1) & 1);
    const __half* Ab = As + buf * GST;
    const __half* Bb = Bs + buf * GST;

#pragma unroll
    for (int ksp = 0; ksp < 4; ksp++) {
      int k0 = ksp * 16;
      unsigned a[4][4];
#pragma unroll
      for (int mt = 0; mt < 4; mt++) {
        int row = wm * 64 + mt * 16 + koct + lrow;
        ldsm4(a[mt], Ab + row * 72 + k0 + hoct);
      }
      unsigned bb[4][4];
#pragma unroll
      for (int np = 0; np < 4; np++) {
        int n = wn * 64 + np * 16 + hoct + lrow;
        ldsm4(bb[np], Bb + n * 72 + k0 + koct);
      }
#pragma unroll
      for (int mt = 0; mt < 4; mt++) {
#pragma unroll
        for (int np = 0; np < 4; np++) {
          mma_f16(acc[mt][2 * np],     a[mt], bb[np]);
          mma_f16(acc[mt][2 * np + 1], a[mt], bb[np] + 2);
        }
      }
    }

    __syncthreads();  // all reads of buf done before it is re-staged
    if (kt + 2 < NT) stage((kt + 2) * 64, buf);
  }

#pragma unroll
  for (int mt = 0; mt < 4; mt++) {
    long row = m0 + wm * 64 + mt * 16 + g;
#pragma unroll
    for (int nt = 0; nt < 8; nt++) {
      int col = n0 + wn * 64 + nt * 8 + 2 * tg;
      float2 bb = *(const float2*)(bias + col);
      float v00 = (acc[mt][nt][0] + bb.x) * oscale;
      float v01 = (acc[mt][nt][1] + bb.y) * oscale;
      float v10 = (acc[mt][nt][2] + bb.x) * oscale;
      float v11 = (acc[mt][nt][3] + bb.y) * oscale;
      if (OUTH) {
        __half* C = (__half*)Cv;
        *(__half2*)(C + row * DM_ + col)       = __floats2half2_rn(v00, v01);
        *(__half2*)(C + (row + 8) * DM_ + col) = __floats2half2_rn(v10, v11);
      } else {
        float* C = (float*)Cv;
        *(float2*)(C + row * DM_ + col)       = make_float2(v00, v01);
        *(float2*)(C + (row + 8) * DM_ + col) = make_float2(v10, v11);
      }
    }
  }
}

#define QSCALE 0.18033688011112042592f  // (1/sqrt(64)) * log2(e)
#define GEMM_SMEM (4 * GST * 2)         // 73728 B

__global__ __launch_bounds__(128) void gemm_qkv_kernel(
    const __half* __restrict__ A, const __half* __restrict__ Wqt,
    const __half* __restrict__ Wkt, const __half* __restrict__ Wvt,
    const float* __restrict__ bq, const float* __restrict__ bk,
    const float* __restrict__ bv, __half* __restrict__ Qo,
    __half* __restrict__ Ko, __half* __restrict__ Vo) {
  const __half* Wt = (blockIdx.z == 0) ? Wqt : (blockIdx.z == 1) ? Wkt : Wvt;
  const float* bias = (blockIdx.z == 0) ? bq : (blockIdx.z == 1) ? bk : bv;
  __half* C = (blockIdx.z == 0) ? Qo : (blockIdx.z == 1) ? Ko : Vo;
  float sc = (blockIdx.z == 0) ? QSCALE : 1.0f;
  gemm_body_h<1>(A, Wt, bias, C, sc, (long)blockIdx.y * 128, blockIdx.x * 128);
}

__global__ __launch_bounds__(128) void gemm_out_kernel(
    const __half* __restrict__ A, const __half* __restrict__ Wt,
    const float* __restrict__ bias, float* __restrict__ C) {
  gemm_body_h<0>(A, Wt, bias, C, 1.0f, (long)blockIdx.y * 128,
                 blockIdx.x * 128);
}

// ---------------------------------------------------------------------------
// Flash attention, fp16 mma. Staging via cp.async.bulk + mbarrier (one 128B
// row per thread per KV block). Math identical to R6/R9 best.
// ---------------------------------------------------------------------------
__global__ __launch_bounds__(128) void flash_h_kernel(
    const __half* __restrict__ Qg, const __half* __restrict__ Kg,
    const __half* __restrict__ Vg, __half* __restrict__ Og) {
  __shared__ __half Ks[2][64 * 72];
  __shared__ __half Vs[2][64 * 72];
  __shared__ unsigned long long fmb[2];

  const int tid  = threadIdx.x;
  const int lane = tid & 31;
  const int wid  = tid >> 5;
  const int g    = lane >> 2;
  const int tg   = lane & 3;
  const int lrow = lane & 7;
  const int koct = ((lane >> 3) & 1) << 3;
  const int hoct = (lane >> 4) << 3;
  const int bh   = blockIdx.y;
  const int b    = bh >> 4;
  const int h    = bh & 15;
  const int q0   = blockIdx.x * 64;

  const __half* Qb  = Qg + ((long)(b * S_ + q0)) * DM_ + h * HD_;
  const __half* Kb0 = Kg + ((long)b * S_) * DM_ + h * HD_;
  const __half* Vb0 = Vg + ((long)b * S_) * DM_ + h * HD_;
  __half* Ob        = Og + ((long)(b * S_ + q0)) * DM_ + h * HD_;

  unsigned mb0 = (unsigned)__cvta_generic_to_shared(&fmb[0]);
  unsigned mb1 = (unsigned)__cvta_generic_to_shared(&fmb[1]);
  unsigned ksb = (unsigned)__cvta_generic_to_shared(&Ks[0][0]);
  unsigned vsb = (unsigned)__cvta_generic_to_shared(&Vs[0][0]);

  if (tid == 0) {
    mbar_init(mb0, 128);
    mbar_init(mb1, 128);
  }
  __syncthreads();

  // one 128B row per thread: tid<64 -> K row tid, else V row tid-64
  auto stage = [&](int kb, int p) {
    unsigned mb = p ? mb1 : mb0;
    mbar_expect(mb, 128);
    if (tid < 64) {
      cpbulk(ksb + p * 9216 + tid * 144,
             Kb0 + (long)(kb * 64 + tid) * DM_, 128, mb);
    } else {
      cpbulk(vsb + p * 9216 + (tid - 64) * 144,
             Vb0 + (long)(kb * 64 + tid - 64) * DM_, 128, mb);
    }
  };

  unsigned qa[4][4];
  {
    int qrow = wid * 16 + g;
#pragma unroll
    for (int ks = 0; ks < 4; ks++) {
      int c = ks * 16 + 2 * tg;
      qa[ks][0] = *(const unsigned*)(Qb + (long)qrow * DM_ + c);
      qa[ks][1] = *(const unsigned*)(Qb + (long)(qrow + 8) * DM_ + c);
      qa[ks][2] = *(const unsigned*)(Qb + (long)qrow * DM_ + c + 8);
      qa[ks][3] = *(const unsigned*)(Qb + (long)(qrow + 8) * DM_ + c + 8);
    }
  }

  float oacc[8][4];
#pragma unroll
  for (int nt = 0; nt < 8; nt++)
#pragma unroll
    for (int j = 0; j < 4; j++) oacc[nt][j] = 0.f;
  float m0r = -INFINITY, m1r = -INFINITY, l0 = 0.f, l1 = 0.f;

  stage(0, 0);
  stage(1, 1);

  for (int kb = 0; kb < S_ / 64; kb++) {
    const int p = kb & 1;
    mbar_wait(p ? mb1 : mb0, (kb >> 1) & 1);

    float sacc[8][4];
#pragma unroll
    for (int nt = 0; nt < 8; nt++)
#pragma unroll
      for (int j = 0; j < 4; j++) sacc[nt][j] = 0.f;
#pragma unroll
    for (int np = 0; np < 4; np++) {
#pragma unroll
      for (int ks = 0; ks < 4; ks++) {
        unsigned bb[4];
        int n = np * 16 + hoct + lrow;
        ldsm4(bb, &Ks[p][n * 72 + ks * 16 + koct]);
        mma_f16(sacc[2 * np],     qa[ks], bb);
        mma_f16(sacc[2 * np + 1], qa[ks], bb + 2);
      }
    }

    float mx0 = -INFINITY, mx1 = -INFINITY;
#pragma unroll
    for (int nt = 0; nt < 8; nt++) {
      mx0 = fmaxf(mx0, fmaxf(sacc[nt][0], sacc[nt][1]));
      mx1 = fmaxf(mx1, fmaxf(sacc[nt][2], sacc[nt][3]));
    }
#pragma unroll
    for (int off = 1; off <= 2; off <<= 1) {
      mx0 = fmaxf(mx0, __shfl_xor_sync(0xffffffffu, mx0, off));
      mx1 = fmaxf(mx1, __shfl_xor_sync(0xffffffffu, mx1, off));
    }
    float mn0 = fmaxf(m0r, mx0), mn1 = fmaxf(m1r, mx1);
    float al0 = exp2f(m0r - mn0), al1 = exp2f(m1r - mn1);
    m0r = mn0; m1r = mn1;

    float ps0 = 0.f, ps1 = 0.f;
#pragma unroll
    for (int nt = 0; nt < 8; nt++) {
      sacc[nt][0] = exp2f(sacc[nt][0] - mn0);
      sacc[nt][1] = exp2f(sacc[nt][1] - mn0);
      sacc[nt][2] = exp2f(sacc[nt][2] - mn1);
      sacc[nt][3] = exp2f(sacc[nt][3] - mn1);
      ps0 += sacc[nt][0] + sacc[nt][1];
      ps1 += sacc[nt][2] + sacc[nt][3];
    }
#pragma unroll
    for (int off = 1; off <= 2; off <<= 1) {
      ps0 += __shfl_xor_sync(0xffffffffu, ps0, off);
      ps1 += __shfl_xor_sync(0xffffffffu, ps1, off);
    }
    l0 = l0 * al0 + ps0;
    l1 = l1 * al1 + ps1;
#pragma unroll
    for (int nt = 0; nt < 8; nt++) {
      oacc[nt][0] *= al0;
      oacc[nt][1] *= al0;
      oacc[nt][2] *= al1;
      oacc[nt][3] *= al1;
    }

    unsigned pa[4][4];
#pragma unroll
    for (int ks = 0; ks < 4; ks++) {
      pa[ks][0] = pack_h2(sacc[2 * ks][0],     sacc[2 * ks][1]);
      pa[ks][1] = pack_h2(sacc[2 * ks][2],     sacc[2 * ks][3]);
      pa[ks][2] = pack_h2(sacc[2 * ks + 1][0], sacc[2 * ks + 1][1]);
      pa[ks][3] = pack_h2(sacc[2 * ks + 1][2], sacc[2 * ks + 1][3]);
    }

#pragma unroll
    for (int ks = 0; ks < 4; ks++) {
#pragma unroll
      for (int dp = 0; dp < 4; dp++) {
        unsigned vv[4];
        int kv = ks * 16 + koct + lrow;
        int d  = dp * 16 + hoct;
        ldsm4t(vv, &Vs[p][kv * 72 + d]);
        mma_f16(oacc[2 * dp],     pa[ks], vv);
        mma_f16(oacc[2 * dp + 1], pa[ks], vv + 2);
      }
    }

    __syncthreads();  // all reads of buffer p done before re-staging
    if (kb + 2 < S_ / 64) stage(kb + 2, p);
  }

  float inv0 = 1.f / l0, inv1 = 1.f / l1;
  int row = wid * 16 + g;
#pragma unroll
  for (int nt = 0; nt < 8; nt++) {
    int col = nt * 8 + 2 * tg;
    *(__half2*)(Ob + (long)row * DM_ + col) =
        __floats2half2_rn(oacc[nt][0] * inv0, oacc[nt][1] * inv0);
    *(__half2*)(Ob + (long)(row + 8) * DM_ + col) =
        __floats2half2_rn(oacc[nt][2] * inv1, oacc[nt][3] * inv1);
  }
}

// ---------------------------------------------------------------------------
extern "C" void kernel_launch(void* const* d_in, const int* in_sizes, int n_in,
                              void* d_out, int out_size) {
  const float* x  = (const float*)d_in[0];
  const float* Wq = (const float*)d_in[1];
  const float* bq = (const float*)d_in[2];
  const float* Wk = (const float*)d_in[3];
  const float* bk = (const float*)d_in[4];
  const float* Wv = (const float*)d_in[5];
  const float* bv = (const float*)d_in[6];
  const float* Wo = (const float*)d_in[7];
  const float* bo = (const float*)d_in[8];
  float* out = (float*)d_out;

  __half *q, *k, *v, *attn, *xh, *wqt, *wkt, *wvt, *wot;
  cudaGetSymbolAddress((void**)&q, g_q);
  cudaGetSymbolAddress((void**)&k, g_k);
  cudaGetSymbolAddress((void**)&v, g_v);
  cudaGetSymbolAddress((void**)&attn, g_attn);
  cudaGetSymbolAddress((void**)&xh, g_xh);
  cudaGetSymbolAddress((void**)&wqt, g_wqt);
  cudaGetSymbolAddress((void**)&wkt, g_wkt);
  cudaGetSymbolAddress((void**)&wvt, g_wvt);
  cudaGetSymbolAddress((void**)&wot, g_wot);

  f2h_kernel<<<512, 256>>>(x, xh, (long)MROWS * DM_ / 4);
  dim3 tgrid(DM_ / 32, DM_ / 32);
  f2hT_kernel<<<tgrid, 256>>>(Wq, wqt);
  f2hT_kernel<<<tgrid, 256>>>(Wk, wkt);
  f2hT_kernel<<<tgrid, 256>>>(Wv, wvt);
  f2hT_kernel<<<tgrid, 256>>>(Wo, wot);

  cudaFuncSetAttribute(gemm_qkv_kernel,
                       cudaFuncAttributeMaxDynamicSharedMemorySize, GEMM_SMEM);
  cudaFuncSetAttribute(gemm_out_kernel,
                       cudaFuncAttributeMaxDynamicSharedMemorySize, GEMM_SMEM);

  dim3 qkvgrid(DM_ / 128, MROWS / 128, 3);
  gemm_qkv_kernel<<<qkvgrid, 128, GEMM_SMEM>>>(xh, wqt, wkt, wvt, bq, bk, bv,
                                               q, k, v);

  flash_h_kernel<<<dim3(S_ / 64, B_ * H_), 128>>>(q, k, v, attn);

  dim3 ggrid(DM_ / 128, MROWS / 128);
  gemm_out_kernel<<<ggrid, 128, GEMM_SMEM>>>(attn, wot, bo, out);
}

// round 12
// speedup vs baseline: 1.4965x; 1.4965x over previous
#include <cuda_runtime.h>
#include <cuda_fp16.h>
#include <math.h>

#define B_   2
#define S_   4096
#define DM_  1024
#define H_   16
#define HD_  64
#define MROWS (B_ * S_)

// Packed layouts (smem-image, pad stride 72 halves):
//  A-pack (xh, attn): [mblk(64)][kblk(16)][row 128][72]
//  B-pack (weights) : [nblk(8)][kblk(16)][row 128][72]
//  QKV      (q,k,v) : [b*16+h (32)][s 4096][72]
#define TILE_H 9216          // halves per 128x72 tile
#define TILE_B 18432         // bytes per tile
#define KV_ROW 72

__device__ __half g_q[32 * 4096 * KV_ROW];
__device__ __half g_k[32 * 4096 * KV_ROW];
__device__ __half g_v[32 * 4096 * KV_ROW];
__device__ __half g_attn[64 * 16 * TILE_H];
__device__ __half g_xh[64 * 16 * TILE_H];
__device__ __half g_wqt[8 * 16 * TILE_H];
__device__ __half g_wkt[8 * 16 * TILE_H];
__device__ __half g_wvt[8 * 16 * TILE_H];
__device__ __half g_wot[8 * 16 * TILE_H];

__device__ __forceinline__ void mma_f16(float c[4], const unsigned a[4],
                                        const unsigned b[2]) {
  asm volatile(
      "mma.sync.aligned.m16n8k16.row.col.f32.f16.f16.f32 "
      "{%0,%1,%2,%3}, {%4,%5,%6,%7}, {%8,%9}, {%0,%1,%2,%3};"
      : "+f"(c[0]), "+f"(c[1]), "+f"(c[2]), "+f"(c[3])
      : "r"(a[0]), "r"(a[1]), "r"(a[2]), "r"(a[3]), "r"(b[0]), "r"(b[1]));
}

__device__ __forceinline__ void ldsm4(unsigned r[4], const void* p) {
  unsigned a = (unsigned)__cvta_generic_to_shared(p);
  asm volatile(
      "ldmatrix.sync.aligned.m8n8.x4.shared.b16 {%0,%1,%2,%3}, [%4];"
      : "=r"(r[0]), "=r"(r[1]), "=r"(r[2]), "=r"(r[3])
      : "r"(a));
}

__device__ __forceinline__ void ldsm4t(unsigned r[4], const void* p) {
  unsigned a = (unsigned)__cvta_generic_to_shared(p);
  asm volatile(
      "ldmatrix.sync.aligned.m8n8.x4.trans.shared.b16 {%0,%1,%2,%3}, [%4];"
      : "=r"(r[0]), "=r"(r[1]), "=r"(r[2]), "=r"(r[3])
      : "r"(a));
}

__device__ __forceinline__ void cpbulk(unsigned dst_smem, const void* gsrc,
                                       unsigned bytes, unsigned mbar) {
  asm volatile(
      "cp.async.bulk.shared::cluster.global.mbarrier::complete_tx::bytes "
      "[%0], [%1], %2, [%3];"
      ::"r"(dst_smem), "l"(gsrc), "r"(bytes), "r"(mbar) : "memory");
}
__device__ __forceinline__ void mbar_init(unsigned addr, unsigned cnt) {
  asm volatile("mbarrier.init.shared.b64 [%0], %1;" ::"r"(addr), "r"(cnt)
               : "memory");
}
__device__ __forceinline__ void mbar_expect(unsigned addr, unsigned bytes) {
  asm volatile("mbarrier.arrive.expect_tx.shared.b64 _, [%0], %1;"
               ::"r"(addr), "r"(bytes) : "memory");
}
__device__ __forceinline__ void mbar_wait(unsigned addr, unsigned parity) {
  asm volatile(
      "{\n\t.reg .pred P;\n\t"
      "WL%=:\n\t"
      "mbarrier.try_wait.parity.acquire.cta.shared::cta.b64 P, [%0], %1;\n\t"
      "@!P bra WL%=;\n\t}"
      ::"r"(addr), "r"(parity) : "memory");
}

__device__ __forceinline__ unsigned pack_h2(float lo, float hi) {
  __half2 h = __floats2half2_rn(lo, hi);
  return *(unsigned*)&h;
}

// ---------------------------------------------------------------------------
// Pre-pass: x fp32 -> A-packed fp16. One thread = 8 halves (16B write).
// ---------------------------------------------------------------------------
__global__ __launch_bounds__(256) void f2h_pack(const float* __restrict__ in,
                                                __half* __restrict__ out) {
  int idx = blockIdx.x * 256 + threadIdx.x;  // 0 .. 1048575
  int m = idx >> 7;
  int k = (idx & 127) << 3;
  const float4* src = (const float4*)(in + (long)m * DM_ + k);
  float4 v0 = src[0], v1 = src[1];
  __half2 h0 = __floats2half2_rn(v0.x, v0.y);
  __half2 h1 = __floats2half2_rn(v0.z, v0.w);
  __half2 h2 = __floats2half2_rn(v1.x, v1.y);
  __half2 h3 = __floats2half2_rn(v1.z, v1.w);
  long off = ((long)((m >> 7) * 16 + (k >> 6))) * TILE_H + (m & 127) * 72 +
             (k & 63);
  uint4 w;
  w.x = *(unsigned*)&h0;
  w.y = *(unsigned*)&h1;
  w.z = *(unsigned*)&h2;
  w.w = *(unsigned*)&h3;
  *(uint4*)(out + off) = w;
}

// Weights: transpose + fp16 + B-pack. out tile idx = (n>>7)*16 + (k>>6).
__global__ __launch_bounds__(256) void f2hT_pack(
    const float* __restrict__ in, __half* __restrict__ out) {
  __shared__ float t[32][33];
  int k0 = blockIdx.x * 32, n0 = blockIdx.y * 32;
  int tx = threadIdx.x & 31, ty = threadIdx.x >> 5;
#pragma unroll
  for (int i = 0; i < 32; i += 8)
    t[ty + i][tx] = in[(long)(k0 + ty + i) * DM_ + n0 + tx];
  __syncthreads();
#pragma unroll
  for (int i = 0; i < 32; i += 8) {
    int n = n0 + ty + i;
    int k = k0 + tx;
    long off = ((long)((n >> 7) * 16 + (k >> 6))) * TILE_H + (n & 127) * 72 +
               (k & 63);
    out[off] = __float2half_rn(t[tx][ty + i]);
  }
}

// ---------------------------------------------------------------------------
// GEMM: CTA 128x128, 4 warps x (64x64). K staged 64 via ONE 18KB bulk copy
// per matrix per stage (elected thread) + mbarrier. Compute = R9 (best).
// Dynamic smem: [A0][A1][B0][B1] x 9216 halves = 73728 B.
// ---------------------------------------------------------------------------
#define GST TILE_H

template <int OUTH>
__device__ __forceinline__ void gemm_body_h(
    const __half* __restrict__ A, const __half* __restrict__ Wt,
    const float* __restrict__ bias, void* Cv, float oscale) {
  extern __shared__ __half gsm[];
  __shared__ __align__(8) unsigned long long gmb[2];

  const int tid  = threadIdx.x;
  const int lane = tid & 31;
  const int wid  = tid >> 5;
  const int g    = lane >> 2;
  const int tg   = lane & 3;
  const int wm   = wid & 1;
  const int wn   = wid >> 1;
  const int lrow = lane & 7;
  const int koct = ((lane >> 3) & 1) << 3;
  const int hoct = (lane >> 4) << 3;
  const int mblk = blockIdx.y;
  const int nblk = blockIdx.x;

  unsigned mb0 = (unsigned)__cvta_generic_to_shared(&gmb[0]);
  unsigned mb1 = (unsigned)__cvta_generic_to_shared(&gmb[1]);
  unsigned smb = (unsigned)__cvta_generic_to_shared(gsm);

  if (tid == 0) {
    mbar_init(mb0, 1);
    mbar_init(mb1, 1);
  }
  __syncthreads();

  auto stage = [&](int kblk, int buf) {
    if (tid == 0) {
      unsigned mb = buf ? mb1 : mb0;
      mbar_expect(mb, 2 * TILE_B);
      cpbulk(smb + buf * TILE_B, A + ((long)(mblk * 16 + kblk)) * TILE_H,
             TILE_B, mb);
      cpbulk(smb + 2 * TILE_B + buf * TILE_B,
             Wt + ((long)(nblk * 16 + kblk)) * TILE_H, TILE_B, mb);
    }
  };

  float acc[4][8][4];
#pragma unroll
  for (int mt = 0; mt < 4; mt++)
#pragma unroll
    for (int nt = 0; nt < 8; nt++)
#pragma unroll
      for (int j = 0; j < 4; j++) acc[mt][nt][j] = 0.f;

  stage(0, 0);
  stage(1, 1);

  const int NT = DM_ / 64;  // 16
  for (int kt = 0; kt < NT; kt++) {
    const int buf = kt & 1;
    mbar_wait(buf ? mb1 : mb0, (kt >> 1) & 1);
    const __half* Ab = gsm + buf * GST;
    const __half* Bb = gsm + 2 * GST + buf * GST;

#pragma unroll
    for (int ksp = 0; ksp < 4; ksp++) {
      int k0 = ksp * 16;
      unsigned a[4][4];
#pragma unroll
      for (int mt = 0; mt < 4; mt++) {
        int row = wm * 64 + mt * 16 + koct + lrow;
        ldsm4(a[mt], Ab + row * 72 + k0 + hoct);
      }
      unsigned bb[4][4];
#pragma unroll
      for (int np = 0; np < 4; np++) {
        int n = wn * 64 + np * 16 + hoct + lrow;
        ldsm4(bb[np], Bb + n * 72 + k0 + koct);
      }
#pragma unroll
      for (int mt = 0; mt < 4; mt++) {
#pragma unroll
        for (int np = 0; np < 4; np++) {
          mma_f16(acc[mt][2 * np],     a[mt], bb[np]);
          mma_f16(acc[mt][2 * np + 1], a[mt], bb[np] + 2);
        }
      }
    }

    __syncthreads();  // all reads of buf done before it is re-staged
    if (kt + 2 < NT) stage(kt + 2, buf);
  }

#pragma unroll
  for (int mt = 0; mt < 4; mt++) {
    long row0 = (long)mblk * 128 + wm * 64 + mt * 16 + g;
#pragma unroll
    for (int nt = 0; nt < 8; nt++) {
      int col = nblk * 128 + wn * 64 + nt * 8 + 2 * tg;
      float2 bb = *(const float2*)(bias + col);
      float v00 = (acc[mt][nt][0] + bb.x) * oscale;
      float v01 = (acc[mt][nt][1] + bb.y) * oscale;
      float v10 = (acc[mt][nt][2] + bb.x) * oscale;
      float v11 = (acc[mt][nt][3] + bb.y) * oscale;
      if (OUTH) {
        // QKV head-major padded layout: ((b*16+h)*4096 + s)*72 + d
        __half* C = (__half*)Cv;
        int h = col >> 6, d = col & 63;
#pragma unroll
        for (int rr = 0; rr < 2; rr++) {
          long m = row0 + rr * 8;
          int bq = (int)(m >> 12), s = (int)(m & 4095);
          long addr = ((long)(bq * 16 + h) * 4096 + s) * 72 + d;
          *(__half2*)(C + addr) = rr ? __floats2half2_rn(v10, v11)
                                     : __floats2half2_rn(v00, v01);
        }
      } else {
        float* C = (float*)Cv;
        *(float2*)(C + row0 * DM_ + col)       = make_float2(v00, v01);
        *(float2*)(C + (row0 + 8) * DM_ + col) = make_float2(v10, v11);
      }
    }
  }
}

#define QSCALE 0.18033688011112042592f  // (1/sqrt(64)) * log2(e)
#define GEMM_SMEM (4 * TILE_B)          // 73728 B

__global__ __launch_bounds__(128) void gemm_qkv_kernel(
    const __half* __restrict__ A, const __half* __restrict__ Wqt,
    const __half* __restrict__ Wkt, const __half* __restrict__ Wvt,
    const float* __restrict__ bq, const float* __restrict__ bk,
    const float* __restrict__ bv, __half* __restrict__ Qo,
    __half* __restrict__ Ko, __half* __restrict__ Vo) {
  const __half* Wt = (blockIdx.z == 0) ? Wqt : (blockIdx.z == 1) ? Wkt : Wvt;
  const float* bias = (blockIdx.z == 0) ? bq : (blockIdx.z == 1) ? bk : bv;
  __half* C = (blockIdx.z == 0) ? Qo : (blockIdx.z == 1) ? Ko : Vo;
  float sc = (blockIdx.z == 0) ? QSCALE : 1.0f;
  gemm_body_h<1>(A, Wt, bias, C, sc);
}

__global__ __launch_bounds__(128) void gemm_out_kernel(
    const __half* __restrict__ A, const __half* __restrict__ Wt,
    const float* __restrict__ bias, float* __restrict__ C) {
  gemm_body_h<0>(A, Wt, bias, C, 1.0f);
}

// ---------------------------------------------------------------------------
// Flash attention. K/V staged via ONE 9KB bulk copy each per block (elected
// thread) + mbarrier. Compute identical to R9 best. Output -> A-packed attn.
// ---------------------------------------------------------------------------
__global__ __launch_bounds__(128) void flash_h_kernel(
    const __half* __restrict__ Qg, const __half* __restrict__ Kg,
    const __half* __restrict__ Vg, __half* __restrict__ attn) {
  __shared__ __align__(16) __half Ks[2][64 * 72];
  __shared__ __align__(16) __half Vs[2][64 * 72];
  __shared__ __align__(8) unsigned long long fmb[2];

  const int tid  = threadIdx.x;
  const int lane = tid & 31;
  const int wid  = tid >> 5;
  const int g    = lane >> 2;
  const int tg   = lane & 3;
  const int lrow = lane & 7;
  const int koct = ((lane >> 3) & 1) << 3;
  const int hoct = (lane >> 4) << 3;
  const int bh   = blockIdx.y;   // b*16 + h
  const int q0   = blockIdx.x * 64;

  const __half* Qb  = Qg + ((long)bh * 4096 + q0) * 72;
  const __half* Kb0 = Kg + (long)bh * 4096 * 72;
  const __half* Vb0 = Vg + (long)bh * 4096 * 72;

  unsigned mb0 = (unsigned)__cvta_generic_to_shared(&fmb[0]);
  unsigned mb1 = (unsigned)__cvta_generic_to_shared(&fmb[1]);
  unsigned ksb = (unsigned)__cvta_generic_to_shared(&Ks[0][0]);
  unsigned vsb = (unsigned)__cvta_generic_to_shared(&Vs[0][0]);

  if (tid == 0) {
    mbar_init(mb0, 1);
    mbar_init(mb1, 1);
  }
  __syncthreads();

  auto stage = [&](int kb, int p) {
    if (tid == 0) {
      unsigned mb = p ? mb1 : mb0;
      mbar_expect(mb, 2 * 9216);
      cpbulk(ksb + p * 9216, Kb0 + (long)(kb * 64) * 72, 9216, mb);
      cpbulk(vsb + p * 9216, Vb0 + (long)(kb * 64) * 72, 9216, mb);
    }
  };

  unsigned qa[4][4];
  {
    int qrow = wid * 16 + g;
#pragma unroll
    for (int ks = 0; ks < 4; ks++) {
      int c = ks * 16 + 2 * tg;
      qa[ks][0] = *(const unsigned*)(Qb + (long)qrow * 72 + c);
      qa[ks][1] = *(const unsigned*)(Qb + (long)(qrow + 8) * 72 + c);
      qa[ks][2] = *(const unsigned*)(Qb + (long)qrow * 72 + c + 8);
      qa[ks][3] = *(const unsigned*)(Qb + (long)(qrow + 8) * 72 + c + 8);
    }
  }

  float oacc[8][4];
#pragma unroll
  for (int nt = 0; nt < 8; nt++)
#pragma unroll
    for (int j = 0; j < 4; j++) oacc[nt][j] = 0.f;
  float m0r = -INFINITY, m1r = -INFINITY, l0 = 0.f, l1 = 0.f;

  stage(0, 0);
  stage(1, 1);

  for (int kb = 0; kb < S_ / 64; kb++) {
    const int p = kb & 1;
    mbar_wait(p ? mb1 : mb0, (kb >> 1) & 1);

    float sacc[8][4];
#pragma unroll
    for (int nt = 0; nt < 8; nt++)
#pragma unroll
      for (int j = 0; j < 4; j++) sacc[nt][j] = 0.f;
#pragma unroll
    for (int np = 0; np < 4; np++) {
#pragma unroll
      for (int ks = 0; ks < 4; ks++) {
        unsigned bb[4];
        int n = np * 16 + hoct + lrow;
        ldsm4(bb, &Ks[p][n * 72 + ks * 16 + koct]);
        mma_f16(sacc[2 * np],     qa[ks], bb);
        mma_f16(sacc[2 * np + 1], qa[ks], bb + 2);
      }
    }

    float mx0 = -INFINITY, mx1 = -INFINITY;
#pragma unroll
    for (int nt = 0; nt < 8; nt++) {
      mx0 = fmaxf(mx0, fmaxf(sacc[nt][0], sacc[nt][1]));
      mx1 = fmaxf(mx1, fmaxf(sacc[nt][2], sacc[nt][3]));
    }
#pragma unroll
    for (int off = 1; off <= 2; off <<= 1) {
      mx0 = fmaxf(mx0, __shfl_xor_sync(0xffffffffu, mx0, off));
      mx1 = fmaxf(mx1, __shfl_xor_sync(0xffffffffu, mx1, off));
    }
    float mn0 = fmaxf(m0r, mx0), mn1 = fmaxf(m1r, mx1);
    float al0 = exp2f(m0r - mn0), al1 = exp2f(m1r - mn1);
    m0r = mn0; m1r = mn1;

    float ps0 = 0.f, ps1 = 0.f;
#pragma unroll
    for (int nt = 0; nt < 8; nt++) {
      sacc[nt][0] = exp2f(sacc[nt][0] - mn0);
      sacc[nt][1] = exp2f(sacc[nt][1] - mn0);
      sacc[nt][2] = exp2f(sacc[nt][2] - mn1);
      sacc[nt][3] = exp2f(sacc[nt][3] - mn1);
      ps0 += sacc[nt][0] + sacc[nt][1];
      ps1 += sacc[nt][2] + sacc[nt][3];
    }
#pragma unroll
    for (int off = 1; off <= 2; off <<= 1) {
      ps0 += __shfl_xor_sync(0xffffffffu, ps0, off);
      ps1 += __shfl_xor_sync(0xffffffffu, ps1, off);
    }
    l0 = l0 * al0 + ps0;
    l1 = l1 * al1 + ps1;
#pragma unroll
    for (int nt = 0; nt < 8; nt++) {
      oacc[nt][0] *= al0;
      oacc[nt][1] *= al0;
      oacc[nt][2] *= al1;
      oacc[nt][3] *= al1;
    }

    unsigned pa[4][4];
#pragma unroll
    for (int ks = 0; ks < 4; ks++) {
      pa[ks][0] = pack_h2(sacc[2 * ks][0],     sacc[2 * ks][1]);
      pa[ks][1] = pack_h2(sacc[2 * ks][2],     sacc[2 * ks][3]);
      pa[ks][2] = pack_h2(sacc[2 * ks + 1][0], sacc[2 * ks + 1][1]);
      pa[ks][3] = pack_h2(sacc[2 * ks + 1][2], sacc[2 * ks + 1][3]);
    }

#pragma unroll
    for (int ks = 0; ks < 4; ks++) {
#pragma unroll
      for (int dp = 0; dp < 4; dp++) {
        unsigned vv[4];
        int kv = ks * 16 + koct + lrow;
        int d  = dp * 16 + hoct;
        ldsm4t(vv, &Vs[p][kv * 72 + d]);
        mma_f16(oacc[2 * dp],     pa[ks], vv);
        mma_f16(oacc[2 * dp + 1], pa[ks], vv + 2);
      }
    }

    __syncthreads();  // all reads of buffer p done before re-staging
    if (kb + 2 < S_ / 64) stage(kb + 2, p);
  }

  // epilogue: normalize, write A-packed attn tiles
  float inv0 = 1.f / l0, inv1 = 1.f / l1;
  const int b = bh >> 4, h = bh & 15;
  int row = wid * 16 + g;
#pragma unroll
  for (int nt = 0; nt < 8; nt++) {
    int col = nt * 8 + 2 * tg;
#pragma unroll
    for (int rr = 0; rr < 2; rr++) {
      int m = b * 4096 + q0 + row + rr * 8;
      long addr = ((long)((m >> 7) * 16 + h)) * TILE_H + (m & 127) * 72 + col;
      *(__half2*)(attn + addr) =
          rr ? __floats2half2_rn(oacc[nt][2] * inv1, oacc[nt][3] * inv1)
             : __floats2half2_rn(oacc[nt][0] * inv0, oacc[nt][1] * inv0);
    }
  }
}

// ---------------------------------------------------------------------------
extern "C" void kernel_launch(void* const* d_in, const int* in_sizes, int n_in,
                              void* d_out, int out_size) {
  const float* x  = (const float*)d_in[0];
  const float* Wq = (const float*)d_in[1];
  const float* bq = (const float*)d_in[2];
  const float* Wk = (const float*)d_in[3];
  const float* bk = (const float*)d_in[4];
  const float* Wv = (const float*)d_in[5];
  const float* bv = (const float*)d_in[6];
  const float* Wo = (const float*)d_in[7];
  const float* bo = (const float*)d_in[8];
  float* out = (float*)d_out;

  __half *q, *k, *v, *attn, *xh, *wqt, *wkt, *wvt, *wot;
  cudaGetSymbolAddress((void**)&q, g_q);
  cudaGetSymbolAddress((void**)&k, g_k);
  cudaGetSymbolAddress((void**)&v, g_v);
  cudaGetSymbolAddress((void**)&attn, g_attn);
  cudaGetSymbolAddress((void**)&xh, g_xh);
  cudaGetSymbolAddress((void**)&wqt, g_wqt);
  cudaGetSymbolAddress((void**)&wkt, g_wkt);
  cudaGetSymbolAddress((void**)&wvt, g_wvt);
  cudaGetSymbolAddress((void**)&wot, g_wot);

  f2h_pack<<<MROWS * DM_ / 8 / 256, 256>>>(x, xh);
  dim3 tgrid(DM_ / 32, DM_ / 32);
  f2hT_pack<<<tgrid, 256>>>(Wq, wqt);
  f2hT_pack<<<tgrid, 256>>>(Wk, wkt);
  f2hT_pack<<<tgrid, 256>>>(Wv, wvt);
  f2hT_pack<<<tgrid, 256>>>(Wo, wot);

  cudaFuncSetAttribute(gemm_qkv_kernel,
                       cudaFuncAttributeMaxDynamicSharedMemorySize, GEMM_SMEM);
  cudaFuncSetAttribute(gemm_out_kernel,
                       cudaFuncAttributeMaxDynamicSharedMemorySize, GEMM_SMEM);

  dim3 qkvgrid(DM_ / 128, MROWS / 128, 3);
  gemm_qkv_kernel<<<qkvgrid, 128, GEMM_SMEM>>>(xh, wqt, wkt, wvt, bq, bk, bv,
                                               q, k, v);

  flash_h_kernel<<<dim3(S_ / 64, B_ * H_), 128>>>(q, k, v, attn);

  dim3 ggrid(DM_ / 128, MROWS / 128);
  gemm_out_kernel<<<ggrid, 128, GEMM_SMEM>>>(attn, wot, bo, out);
}

// round 13
// speedup vs baseline: 1.5354x; 1.0260x over previous
#include <cuda_runtime.h>
#include <cuda_fp16.h>
#include <math.h>

#define B_   2
#define S_   4096
#define DM_  1024
#define H_   16
#define HD_  64
#define MROWS (B_ * S_)

// Packed layouts (smem-image, pad stride 72 halves):
//  A-pack (xh, attn): [mblk(64)][kblk(16)][row 128][72]
//  B-pack (weights) : [nblk(8)][kblk(16)][row 128][72]
//  QKV      (q,k,v) : [b*16+h (32)][s 4096][72]
#define TILE_H 9216          // halves per 128x72 tile
#define TILE_B 18432         // bytes per tile
#define KV_ROW 72

__device__ __half g_q[32 * 4096 * KV_ROW];
__device__ __half g_k[32 * 4096 * KV_ROW];
__device__ __half g_v[32 * 4096 * KV_ROW];
__device__ __half g_attn[64 * 16 * TILE_H];
__device__ __half g_xh[64 * 16 * TILE_H];
__device__ __half g_wqt[8 * 16 * TILE_H];
__device__ __half g_wkt[8 * 16 * TILE_H];
__device__ __half g_wvt[8 * 16 * TILE_H];
__device__ __half g_wot[8 * 16 * TILE_H];

__device__ __forceinline__ void mma_f16(float c[4], const unsigned a[4],
                                        const unsigned b[2]) {
  asm volatile(
      "mma.sync.aligned.m16n8k16.row.col.f32.f16.f16.f32 "
      "{%0,%1,%2,%3}, {%4,%5,%6,%7}, {%8,%9}, {%0,%1,%2,%3};"
      : "+f"(c[0]), "+f"(c[1]), "+f"(c[2]), "+f"(c[3])
      : "r"(a[0]), "r"(a[1]), "r"(a[2]), "r"(a[3]), "r"(b[0]), "r"(b[1]));
}

__device__ __forceinline__ void ldsm4(unsigned r[4], const void* p) {
  unsigned a = (unsigned)__cvta_generic_to_shared(p);
  asm volatile(
      "ldmatrix.sync.aligned.m8n8.x4.shared.b16 {%0,%1,%2,%3}, [%4];"
      : "=r"(r[0]), "=r"(r[1]), "=r"(r[2]), "=r"(r[3])
      : "r"(a));
}

__device__ __forceinline__ void ldsm4t(unsigned r[4], const void* p) {
  unsigned a = (unsigned)__cvta_generic_to_shared(p);
  asm volatile(
      "ldmatrix.sync.aligned.m8n8.x4.trans.shared.b16 {%0,%1,%2,%3}, [%4];"
      : "=r"(r[0]), "=r"(r[1]), "=r"(r[2]), "=r"(r[3])
      : "r"(a));
}

__device__ __forceinline__ void cpbulk(unsigned dst_smem, const void* gsrc,
                                       unsigned bytes, unsigned mbar) {
  asm volatile(
      "cp.async.bulk.shared::cluster.global.mbarrier::complete_tx::bytes "
      "[%0], [%1], %2, [%3];"
      ::"r"(dst_smem), "l"(gsrc), "r"(bytes), "r"(mbar) : "memory");
}
__device__ __forceinline__ void mbar_init(unsigned addr, unsigned cnt) {
  asm volatile("mbarrier.init.shared.b64 [%0], %1;" ::"r"(addr), "r"(cnt)
               : "memory");
}
__device__ __forceinline__ void mbar_expect(unsigned addr, unsigned bytes) {
  asm volatile("mbarrier.arrive.expect_tx.shared.b64 _, [%0], %1;"
               ::"r"(addr), "r"(bytes) : "memory");
}
__device__ __forceinline__ void mbar_wait(unsigned addr, unsigned parity) {
  asm volatile(
      "{\n\t.reg .pred P;\n\t"
      "WL%=:\n\t"
      "mbarrier.try_wait.parity.acquire.cta.shared::cta.b64 P, [%0], %1;\n\t"
      "@!P bra WL%=;\n\t}"
      ::"r"(addr), "r"(parity) : "memory");
}

__device__ __forceinline__ unsigned pack_h2(float lo, float hi) {
  __half2 h = __floats2half2_rn(lo, hi);
  return *(unsigned*)&h;
}

// ---------------------------------------------------------------------------
// Pre-pass: x fp32 -> A-packed fp16. One thread = 8 halves (16B write).
// ---------------------------------------------------------------------------
__global__ __launch_bounds__(256) void f2h_pack(const float* __restrict__ in,
                                                __half* __restrict__ out) {
  int idx = blockIdx.x * 256 + threadIdx.x;
  int m = idx >> 7;
  int k = (idx & 127) << 3;
  const float4* src = (const float4*)(in + (long)m * DM_ + k);
  float4 v0 = src[0], v1 = src[1];
  __half2 h0 = __floats2half2_rn(v0.x, v0.y);
  __half2 h1 = __floats2half2_rn(v0.z, v0.w);
  __half2 h2 = __floats2half2_rn(v1.x, v1.y);
  __half2 h3 = __floats2half2_rn(v1.z, v1.w);
  long off = ((long)((m >> 7) * 16 + (k >> 6))) * TILE_H + (m & 127) * 72 +
             (k & 63);
  uint4 w;
  w.x = *(unsigned*)&h0;
  w.y = *(unsigned*)&h1;
  w.z = *(unsigned*)&h2;
  w.w = *(unsigned*)&h3;
  *(uint4*)(out + off) = w;
}

// Weights: transpose + fp16 + B-pack, fused over grid.z (4 weights).
__global__ __launch_bounds__(256) void f2hT_pack4(
    const float* __restrict__ Wq, const float* __restrict__ Wk,
    const float* __restrict__ Wv, const float* __restrict__ Wo,
    __half* __restrict__ oq, __half* __restrict__ ok,
    __half* __restrict__ ov, __half* __restrict__ oo) {
  const float* in = (blockIdx.z == 0) ? Wq : (blockIdx.z == 1) ? Wk
                    : (blockIdx.z == 2) ? Wv : Wo;
  __half* out = (blockIdx.z == 0) ? oq : (blockIdx.z == 1) ? ok
                : (blockIdx.z == 2) ? ov : oo;
  __shared__ float t[32][33];
  int k0 = blockIdx.x * 32, n0 = blockIdx.y * 32;
  int tx = threadIdx.x & 31, ty = threadIdx.x >> 5;
#pragma unroll
  for (int i = 0; i < 32; i += 8)
    t[ty + i][tx] = in[(long)(k0 + ty + i) * DM_ + n0 + tx];
  __syncthreads();
#pragma unroll
  for (int i = 0; i < 32; i += 8) {
    int n = n0 + ty + i;
    int k = k0 + tx;
    long off = ((long)((n >> 7) * 16 + (k >> 6))) * TILE_H + (n & 127) * 72 +
               (k & 63);
    out[off] = __float2half_rn(t[tx][ty + i]);
  }
}

// ---------------------------------------------------------------------------
// GEMM: CTA 128x128, 4 warps x (64x64). 3-stage bulk-copy pipeline; stage
// issued BEFORE compute each iteration (wait -> sync -> issue k+2 -> compute).
// Dynamic smem: 3 stages x (A + B tile) = 110592 B (2 CTAs/SM).
// ---------------------------------------------------------------------------
#define GST TILE_H

template <int OUTH>
__device__ __forceinline__ void gemm_body_h(
    const __half* __restrict__ A, const __half* __restrict__ Wt,
    const float* __restrict__ bias, void* Cv, float oscale) {
  extern __shared__ __half gsm[];  // [3][A tile | B tile]
  __shared__ __align__(8) unsigned long long gmb[3];

  const int tid  = threadIdx.x;
  const int lane = tid & 31;
  const int wid  = tid >> 5;
  const int g    = lane >> 2;
  const int tg   = lane & 3;
  const int wm   = wid & 1;
  const int wn   = wid >> 1;
  const int lrow = lane & 7;
  const int koct = ((lane >> 3) & 1) << 3;
  const int hoct = (lane >> 4) << 3;
  const int mblk = blockIdx.y;
  const int nblk = blockIdx.x;

  unsigned mbb = (unsigned)__cvta_generic_to_shared(&gmb[0]);
  unsigned smb = (unsigned)__cvta_generic_to_shared(gsm);

  if (tid == 0) {
#pragma unroll
    for (int i = 0; i < 3; i++) mbar_init(mbb + 8 * i, 1);
  }
  __syncthreads();

  auto stage = [&](int kblk) {
    if (tid == 0) {
      int buf = kblk % 3;
      unsigned mb = mbb + 8 * buf;
      mbar_expect(mb, 2 * TILE_B);
      cpbulk(smb + buf * 2 * TILE_B, A + ((long)(mblk * 16 + kblk)) * TILE_H,
             TILE_B, mb);
      cpbulk(smb + buf * 2 * TILE_B + TILE_B,
             Wt + ((long)(nblk * 16 + kblk)) * TILE_H, TILE_B, mb);
    }
  };

  float acc[4][8][4];
#pragma unroll
  for (int mt = 0; mt < 4; mt++)
#pragma unroll
    for (int nt = 0; nt < 8; nt++)
#pragma unroll
      for (int j = 0; j < 4; j++) acc[mt][nt][j] = 0.f;

  stage(0);
  stage(1);

  const int NT = DM_ / 64;  // 16
  for (int kt = 0; kt < NT; kt++) {
    const int buf = kt % 3;
    mbar_wait(mbb + 8 * buf, (kt / 3) & 1);
    __syncthreads();  // all warps done reading buffer (kt+2)%3 (iter kt-1)
    if (kt + 2 < NT) stage(kt + 2);

    const __half* Ab = gsm + buf * 2 * GST;
    const __half* Bb = Ab + GST;

#pragma unroll
    for (int ksp = 0; ksp < 4; ksp++) {
      int k0 = ksp * 16;
      unsigned a[4][4];
#pragma unroll
      for (int mt = 0; mt < 4; mt++) {
        int row = wm * 64 + mt * 16 + koct + lrow;
        ldsm4(a[mt], Ab + row * 72 + k0 + hoct);
      }
      unsigned bb[4][4];
#pragma unroll
      for (int np = 0; np < 4; np++) {
        int n = wn * 64 + np * 16 + hoct + lrow;
        ldsm4(bb[np], Bb + n * 72 + k0 + koct);
      }
#pragma unroll
      for (int mt = 0; mt < 4; mt++) {
#pragma unroll
        for (int np = 0; np < 4; np++) {
          mma_f16(acc[mt][2 * np],     a[mt], bb[np]);
          mma_f16(acc[mt][2 * np + 1], a[mt], bb[np] + 2);
        }
      }
    }
  }

#pragma unroll
  for (int mt = 0; mt < 4; mt++) {
    long row0 = (long)mblk * 128 + wm * 64 + mt * 16 + g;
#pragma unroll
    for (int nt = 0; nt < 8; nt++) {
      int col = nblk * 128 + wn * 64 + nt * 8 + 2 * tg;
      float2 bb = *(const float2*)(bias + col);
      float v00 = (acc[mt][nt][0] + bb.x) * oscale;
      float v01 = (acc[mt][nt][1] + bb.y) * oscale;
      float v10 = (acc[mt][nt][2] + bb.x) * oscale;
      float v11 = (acc[mt][nt][3] + bb.y) * oscale;
      if (OUTH) {
        __half* C = (__half*)Cv;
        int h = col >> 6, d = col & 63;
#pragma unroll
        for (int rr = 0; rr < 2; rr++) {
          long m = row0 + rr * 8;
          int bq = (int)(m >> 12), s = (int)(m & 4095);
          long addr = ((long)(bq * 16 + h) * 4096 + s) * 72 + d;
          *(__half2*)(C + addr) = rr ? __floats2half2_rn(v10, v11)
                                     : __floats2half2_rn(v00, v01);
        }
      } else {
        float* C = (float*)Cv;
        *(float2*)(C + row0 * DM_ + col)       = make_float2(v00, v01);
        *(float2*)(C + (row0 + 8) * DM_ + col) = make_float2(v10, v11);
      }
    }
  }
}

#define QSCALE 0.18033688011112042592f  // (1/sqrt(64)) * log2(e)
#define GEMM_SMEM (6 * TILE_B)          // 110592 B

__global__ __launch_bounds__(128) void gemm_qkv_kernel(
    const __half* __restrict__ A, const __half* __restrict__ Wqt,
    const __half* __restrict__ Wkt, const __half* __restrict__ Wvt,
    const float* __restrict__ bq, const float* __restrict__ bk,
    const float* __restrict__ bv, __half* __restrict__ Qo,
    __half* __restrict__ Ko, __half* __restrict__ Vo) {
  const __half* Wt = (blockIdx.z == 0) ? Wqt : (blockIdx.z == 1) ? Wkt : Wvt;
  const float* bias = (blockIdx.z == 0) ? bq : (blockIdx.z == 1) ? bk : bv;
  __half* C = (blockIdx.z == 0) ? Qo : (blockIdx.z == 1) ? Ko : Vo;
  float sc = (blockIdx.z == 0) ? QSCALE : 1.0f;
  gemm_body_h<1>(A, Wt, bias, C, sc);
}

__global__ __launch_bounds__(128) void gemm_out_kernel(
    const __half* __restrict__ A, const __half* __restrict__ Wt,
    const float* __restrict__ bias, float* __restrict__ C) {
  gemm_body_h<0>(A, Wt, bias, C, 1.0f);
}

// ---------------------------------------------------------------------------
// Flash attention. 3-stage K/V bulk-copy pipeline, stage issued before
// compute. Compute identical to R9/R12. Output -> A-packed attn.
// ---------------------------------------------------------------------------
__global__ __launch_bounds__(128) void flash_h_kernel(
    const __half* __restrict__ Qg, const __half* __restrict__ Kg,
    const __half* __restrict__ Vg, __half* __restrict__ attn) {
  __shared__ __align__(16) __half Ks[3][64 * 72];
  __shared__ __align__(16) __half Vs[3][64 * 72];
  __shared__ __align__(8) unsigned long long fmb[3];

  const int tid  = threadIdx.x;
  const int lane = tid & 31;
  const int wid  = tid >> 5;
  const int g    = lane >> 2;
  const int tg   = lane & 3;
  const int lrow = lane & 7;
  const int koct = ((lane >> 3) & 1) << 3;
  const int hoct = (lane >> 4) << 3;
  const int bh   = blockIdx.y;   // b*16 + h
  const int q0   = blockIdx.x * 64;

  const __half* Qb  = Qg + ((long)bh * 4096 + q0) * 72;
  const __half* Kb0 = Kg + (long)bh * 4096 * 72;
  const __half* Vb0 = Vg + (long)bh * 4096 * 72;

  unsigned mbb = (unsigned)__cvta_generic_to_shared(&fmb[0]);
  unsigned ksb = (unsigned)__cvta_generic_to_shared(&Ks[0][0]);
  unsigned vsb = (unsigned)__cvta_generic_to_shared(&Vs[0][0]);

  if (tid == 0) {
#pragma unroll
    for (int i = 0; i < 3; i++) mbar_init(mbb + 8 * i, 1);
  }
  __syncthreads();

  auto stage = [&](int kb) {
    if (tid == 0) {
      int p = kb % 3;
      unsigned mb = mbb + 8 * p;
      mbar_expect(mb, 2 * 9216);
      cpbulk(ksb + p * 9216, Kb0 + (long)(kb * 64) * 72, 9216, mb);
      cpbulk(vsb + p * 9216, Vb0 + (long)(kb * 64) * 72, 9216, mb);
    }
  };

  unsigned qa[4][4];
  {
    int qrow = wid * 16 + g;
#pragma unroll
    for (int ks = 0; ks < 4; ks++) {
      int c = ks * 16 + 2 * tg;
      qa[ks][0] = *(const unsigned*)(Qb + (long)qrow * 72 + c);
      qa[ks][1] = *(const unsigned*)(Qb + (long)(qrow + 8) * 72 + c);
      qa[ks][2] = *(const unsigned*)(Qb + (long)qrow * 72 + c + 8);
      qa[ks][3] = *(const unsigned*)(Qb + (long)(qrow + 8) * 72 + c + 8);
    }
  }

  float oacc[8][4];
#pragma unroll
  for (int nt = 0; nt < 8; nt++)
#pragma unroll
    for (int j = 0; j < 4; j++) oacc[nt][j] = 0.f;
  float m0r = -INFINITY, m1r = -INFINITY, l0 = 0.f, l1 = 0.f;

  stage(0);
  stage(1);

  for (int kb = 0; kb < S_ / 64; kb++) {
    const int p = kb % 3;
    mbar_wait(mbb + 8 * p, (kb / 3) & 1);
    __syncthreads();  // all warps done reading buffer (kb+2)%3
    if (kb + 2 < S_ / 64) stage(kb + 2);

    float sacc[8][4];
#pragma unroll
    for (int nt = 0; nt < 8; nt++)
#pragma unroll
      for (int j = 0; j < 4; j++) sacc[nt][j] = 0.f;
#pragma unroll
    for (int np = 0; np < 4; np++) {
#pragma unroll
      for (int ks = 0; ks < 4; ks++) {
        unsigned bb[4];
        int n = np * 16 + hoct + lrow;
        ldsm4(bb, &Ks[p][n * 72 + ks * 16 + koct]);
        mma_f16(sacc[2 * np],     qa[ks], bb);
        mma_f16(sacc[2 * np + 1], qa[ks], bb + 2);
      }
    }

    float mx0 = -INFINITY, mx1 = -INFINITY;
#pragma unroll
    for (int nt = 0; nt < 8; nt++) {
      mx0 = fmaxf(mx0, fmaxf(sacc[nt][0], sacc[nt][1]));
      mx1 = fmaxf(mx1, fmaxf(sacc[nt][2], sacc[nt][3]));
    }
#pragma unroll
    for (int off = 1; off <= 2; off <<= 1) {
      mx0 = fmaxf(mx0, __shfl_xor_sync(0xffffffffu, mx0, off));
      mx1 = fmaxf(mx1, __shfl_xor_sync(0xffffffffu, mx1, off));
    }
    float mn0 = fmaxf(m0r, mx0), mn1 = fmaxf(m1r, mx1);
    float al0 = exp2f(m0r - mn0), al1 = exp2f(m1r - mn1);
    m0r = mn0; m1r = mn1;

    float ps0 = 0.f, ps1 = 0.f;
#pragma unroll
    for (int nt = 0; nt < 8; nt++) {
      sacc[nt][0] = exp2f(sacc[nt][0] - mn0);
      sacc[nt][1] = exp2f(sacc[nt][1] - mn0);
      sacc[nt][2] = exp2f(sacc[nt][2] - mn1);
      sacc[nt][3] = exp2f(sacc[nt][3] - mn1);
      ps0 += sacc[nt][0] + sacc[nt][1];
      ps1 += sacc[nt][2] + sacc[nt][3];
    }
#pragma unroll
    for (int off = 1; off <= 2; off <<= 1) {
      ps0 += __shfl_xor_sync(0xffffffffu, ps0, off);
      ps1 += __shfl_xor_sync(0xffffffffu, ps1, off);
    }
    l0 = l0 * al0 + ps0;
    l1 = l1 * al1 + ps1;
#pragma unroll
    for (int nt = 0; nt < 8; nt++) {
      oacc[nt][0] *= al0;
      oacc[nt][1] *= al0;
      oacc[nt][2] *= al1;
      oacc[nt][3] *= al1;
    }

    unsigned pa[4][4];
#pragma unroll
    for (int ks = 0; ks < 4; ks++) {
      pa[ks][0] = pack_h2(sacc[2 * ks][0],     sacc[2 * ks][1]);
      pa[ks][1] = pack_h2(sacc[2 * ks][2],     sacc[2 * ks][3]);
      pa[ks][2] = pack_h2(sacc[2 * ks + 1][0], sacc[2 * ks + 1][1]);
      pa[ks][3] = pack_h2(sacc[2 * ks + 1][2], sacc[2 * ks + 1][3]);
    }

#pragma unroll
    for (int ks = 0; ks < 4; ks++) {
#pragma unroll
      for (int dp = 0; dp < 4; dp++) {
        unsigned vv[4];
        int kv = ks * 16 + koct + lrow;
        int d  = dp * 16 + hoct;
        ldsm4t(vv, &Vs[p][kv * 72 + d]);
        mma_f16(oacc[2 * dp],     pa[ks], vv);
        mma_f16(oacc[2 * dp + 1], pa[ks], vv + 2);
      }
    }
  }

  // epilogue: normalize, write A-packed attn tiles
  float inv0 = 1.f / l0, inv1 = 1.f / l1;
  const int b = bh >> 4, h = bh & 15;
  int row = wid * 16 + g;
#pragma unroll
  for (int nt = 0; nt < 8; nt++) {
    int col = nt * 8 + 2 * tg;
#pragma unroll
    for (int rr = 0; rr < 2; rr++) {
      int m = b * 4096 + q0 + row + rr * 8;
      long addr = ((long)((m >> 7) * 16 + h)) * TILE_H + (m & 127) * 72 + col;
      *(__half2*)(attn + addr) =
          rr ? __floats2half2_rn(oacc[nt][2] * inv1, oacc[nt][3] * inv1)
             : __floats2half2_rn(oacc[nt][0] * inv0, oacc[nt][1] * inv0);
    }
  }
}

// ---------------------------------------------------------------------------
extern "C" void kernel_launch(void* const* d_in, const int* in_sizes, int n_in,
                              void* d_out, int out_size) {
  const float* x  = (const float*)d_in[0];
  const float* Wq = (const float*)d_in[1];
  const float* bq = (const float*)d_in[2];
  const float* Wk = (const float*)d_in[3];
  const float* bk = (const float*)d_in[4];
  const float* Wv = (const float*)d_in[5];
  const float* bv = (const float*)d_in[6];
  const float* Wo = (const float*)d_in[7];
  const float* bo = (const float*)d_in[8];
  float* out = (float*)d_out;

  __half *q, *k, *v, *attn, *xh, *wqt, *wkt, *wvt, *wot;
  cudaGetSymbolAddress((void**)&q, g_q);
  cudaGetSymbolAddress((void**)&k, g_k);
  cudaGetSymbolAddress((void**)&v, g_v);
  cudaGetSymbolAddress((void**)&attn, g_attn);
  cudaGetSymbolAddress((void**)&xh, g_xh);
  cudaGetSymbolAddress((void**)&wqt, g_wqt);
  cudaGetSymbolAddress((void**)&wkt, g_wkt);
  cudaGetSymbolAddress((void**)&wvt, g_wvt);
  cudaGetSymbolAddress((void**)&wot, g_wot);

  f2h_pack<<<MROWS * DM_ / 8 / 256, 256>>>(x, xh);
  dim3 tgrid(DM_ / 32, DM_ / 32, 4);
  f2hT_pack4<<<tgrid, 256>>>(Wq, Wk, Wv, Wo, wqt, wkt, wvt, wot);

  cudaFuncSetAttribute(gemm_qkv_kernel,
                       cudaFuncAttributeMaxDynamicSharedMemorySize, GEMM_SMEM);
  cudaFuncSetAttribute(gemm_out_kernel,
                       cudaFuncAttributeMaxDynamicSharedMemorySize, GEMM_SMEM);

  dim3 qkvgrid(DM_ / 128, MROWS / 128, 3);
  gemm_qkv_kernel<<<qkvgrid, 128, GEMM_SMEM>>>(xh, wqt, wkt, wvt, bq, bk, bv,
                                               q, k, v);

  flash_h_kernel<<<dim3(S_ / 64, B_ * H_), 128>>>(q, k, v, attn);

  dim3 ggrid(DM_ / 128, MROWS / 128);
  gemm_out_kernel<<<ggrid, 128, GEMM_SMEM>>>(attn, wot, bo, out);
}

// round 14
// speedup vs baseline: 1.5484x; 1.0085x over previous
#include <cuda_runtime.h>
#include <cuda_fp16.h>
#include <math.h>

#define B_   2
#define S_   4096
#define DM_  1024
#define H_   16
#define HD_  64
#define MROWS (B_ * S_)

// Packed layouts (smem-image, pad stride 72 halves):
//  A-pack (xh, attn): [mblk(64)][kblk(16)][row 128][72]
//  B-pack (weights) : [nblk(8)][kblk(16)][row 128][72]
//  QKV      (q,k,v) : [b*16+h (32)][s 4096][72]
#define TILE_H 9216
#define TILE_B 18432
#define KV_ROW 72

__device__ __half g_q[32 * 4096 * KV_ROW];
__device__ __half g_k[32 * 4096 * KV_ROW];
__device__ __half g_v[32 * 4096 * KV_ROW];
__device__ __half g_attn[64 * 16 * TILE_H];
__device__ __half g_xh[64 * 16 * TILE_H];
__device__ __half g_wqt[8 * 16 * TILE_H];
__device__ __half g_wkt[8 * 16 * TILE_H];
__device__ __half g_wvt[8 * 16 * TILE_H];
__device__ __half g_wot[8 * 16 * TILE_H];

__device__ __forceinline__ void mma_f16(float c[4], const unsigned a[4],
                                        const unsigned b[2]) {
  asm volatile(
      "mma.sync.aligned.m16n8k16.row.col.f32.f16.f16.f32 "
      "{%0,%1,%2,%3}, {%4,%5,%6,%7}, {%8,%9}, {%0,%1,%2,%3};"
      : "+f"(c[0]), "+f"(c[1]), "+f"(c[2]), "+f"(c[3])
      : "r"(a[0]), "r"(a[1]), "r"(a[2]), "r"(a[3]), "r"(b[0]), "r"(b[1]));
}

__device__ __forceinline__ void ldsm4(unsigned r[4], const void* p) {
  unsigned a = (unsigned)__cvta_generic_to_shared(p);
  asm volatile(
      "ldmatrix.sync.aligned.m8n8.x4.shared.b16 {%0,%1,%2,%3}, [%4];"
      : "=r"(r[0]), "=r"(r[1]), "=r"(r[2]), "=r"(r[3])
      : "r"(a));
}

__device__ __forceinline__ void ldsm4t(unsigned r[4], const void* p) {
  unsigned a = (unsigned)__cvta_generic_to_shared(p);
  asm volatile(
      "ldmatrix.sync.aligned.m8n8.x4.trans.shared.b16 {%0,%1,%2,%3}, [%4];"
      : "=r"(r[0]), "=r"(r[1]), "=r"(r[2]), "=r"(r[3])
      : "r"(a));
}

__device__ __forceinline__ void cpbulk(unsigned dst_smem, const void* gsrc,
                                       unsigned bytes, unsigned mbar) {
  asm volatile(
      "cp.async.bulk.shared::cluster.global.mbarrier::complete_tx::bytes "
      "[%0], [%1], %2, [%3];"
      ::"r"(dst_smem), "l"(gsrc), "r"(bytes), "r"(mbar) : "memory");
}
__device__ __forceinline__ void mbar_init(unsigned addr, unsigned cnt) {
  asm volatile("mbarrier.init.shared.b64 [%0], %1;" ::"r"(addr), "r"(cnt)
               : "memory");
}
__device__ __forceinline__ void mbar_expect(unsigned addr, unsigned bytes) {
  asm volatile("mbarrier.arrive.expect_tx.shared.b64 _, [%0], %1;"
               ::"r"(addr), "r"(bytes) : "memory");
}
__device__ __forceinline__ void mbar_wait(unsigned addr, unsigned parity) {
  asm volatile(
      "{\n\t.reg .pred P;\n\t"
      "WL%=:\n\t"
      "mbarrier.try_wait.parity.acquire.cta.shared::cta.b64 P, [%0], %1;\n\t"
      "@!P bra WL%=;\n\t}"
      ::"r"(addr), "r"(parity) : "memory");
}

__device__ __forceinline__ unsigned pack_h2(float lo, float hi) {
  __half2 h = __floats2half2_rn(lo, hi);
  return *(unsigned*)&h;
}

// ---------------------------------------------------------------------------
// Pre-pass (unchanged from R13)
// ---------------------------------------------------------------------------
__global__ __launch_bounds__(256) void f2h_pack(const float* __restrict__ in,
                                                __half* __restrict__ out) {
  int idx = blockIdx.x * 256 + threadIdx.x;
  int m = idx >> 7;
  int k = (idx & 127) << 3;
  const float4* src = (const float4*)(in + (long)m * DM_ + k);
  float4 v0 = src[0], v1 = src[1];
  __half2 h0 = __floats2half2_rn(v0.x, v0.y);
  __half2 h1 = __floats2half2_rn(v0.z, v0.w);
  __half2 h2 = __floats2half2_rn(v1.x, v1.y);
  __half2 h3 = __floats2half2_rn(v1.z, v1.w);
  long off = ((long)((m >> 7) * 16 + (k >> 6))) * TILE_H + (m & 127) * 72 +
             (k & 63);
  uint4 w;
  w.x = *(unsigned*)&h0;
  w.y = *(unsigned*)&h1;
  w.z = *(unsigned*)&h2;
  w.w = *(unsigned*)&h3;
  *(uint4*)(out + off) = w;
}

__global__ __launch_bounds__(256) void f2hT_pack4(
    const float* __restrict__ Wq, const float* __restrict__ Wk,
    const float* __restrict__ Wv, const float* __restrict__ Wo,
    __half* __restrict__ oq, __half* __restrict__ ok,
    __half* __restrict__ ov, __half* __restrict__ oo) {
  const float* in = (blockIdx.z == 0) ? Wq : (blockIdx.z == 1) ? Wk
                    : (blockIdx.z == 2) ? Wv : Wo;
  __half* out = (blockIdx.z == 0) ? oq : (blockIdx.z == 1) ? ok
                : (blockIdx.z == 2) ? ov : oo;
  __shared__ float t[32][33];
  int k0 = blockIdx.x * 32, n0 = blockIdx.y * 32;
  int tx = threadIdx.x & 31, ty = threadIdx.x >> 5;
#pragma unroll
  for (int i = 0; i < 32; i += 8)
    t[ty + i][tx] = in[(long)(k0 + ty + i) * DM_ + n0 + tx];
  __syncthreads();
#pragma unroll
  for (int i = 0; i < 32; i += 8) {
    int n = n0 + ty + i;
    int k = k0 + tx;
    long off = ((long)((n >> 7) * 16 + (k >> 6))) * TILE_H + (n & 127) * 72 +
               (k & 63);
    out[off] = __float2half_rn(t[tx][ty + i]);
  }
}

// ---------------------------------------------------------------------------
// GEMM (unchanged from R13): 3-stage bulk pipeline, stage-before-compute.
// ---------------------------------------------------------------------------
#define GST TILE_H

template <int OUTH>
__device__ __forceinline__ void gemm_body_h(
    const __half* __restrict__ A, const __half* __restrict__ Wt,
    const float* __restrict__ bias, void* Cv, float oscale) {
  extern __shared__ __half gsm[];
  __shared__ __align__(8) unsigned long long gmb[3];

  const int tid  = threadIdx.x;
  const int lane = tid & 31;
  const int wid  = tid >> 5;
  const int g    = lane >> 2;
  const int tg   = lane & 3;
  const int wm   = wid & 1;
  const int wn   = wid >> 1;
  const int lrow = lane & 7;
  const int koct = ((lane >> 3) & 1) << 3;
  const int hoct = (lane >> 4) << 3;
  const int mblk = blockIdx.y;
  const int nblk = blockIdx.x;

  unsigned mbb = (unsigned)__cvta_generic_to_shared(&gmb[0]);
  unsigned smb = (unsigned)__cvta_generic_to_shared(gsm);

  if (tid == 0) {
#pragma unroll
    for (int i = 0; i < 3; i++) mbar_init(mbb + 8 * i, 1);
  }
  __syncthreads();

  auto stage = [&](int kblk) {
    if (tid == 0) {
      int buf = kblk % 3;
      unsigned mb = mbb + 8 * buf;
      mbar_expect(mb, 2 * TILE_B);
      cpbulk(smb + buf * 2 * TILE_B, A + ((long)(mblk * 16 + kblk)) * TILE_H,
             TILE_B, mb);
      cpbulk(smb + buf * 2 * TILE_B + TILE_B,
             Wt + ((long)(nblk * 16 + kblk)) * TILE_H, TILE_B, mb);
    }
  };

  float acc[4][8][4];
#pragma unroll
  for (int mt = 0; mt < 4; mt++)
#pragma unroll
    for (int nt = 0; nt < 8; nt++)
#pragma unroll
      for (int j = 0; j < 4; j++) acc[mt][nt][j] = 0.f;

  stage(0);
  stage(1);

  const int NT = DM_ / 64;
  for (int kt = 0; kt < NT; kt++) {
    const int buf = kt % 3;
    mbar_wait(mbb + 8 * buf, (kt / 3) & 1);
    __syncthreads();
    if (kt + 2 < NT) stage(kt + 2);

    const __half* Ab = gsm + buf * 2 * GST;
    const __half* Bb = Ab + GST;

#pragma unroll
    for (int ksp = 0; ksp < 4; ksp++) {
      int k0 = ksp * 16;
      unsigned a[4][4];
#pragma unroll
      for (int mt = 0; mt < 4; mt++) {
        int row = wm * 64 + mt * 16 + koct + lrow;
        ldsm4(a[mt], Ab + row * 72 + k0 + hoct);
      }
      unsigned bb[4][4];
#pragma unroll
      for (int np = 0; np < 4; np++) {
        int n = wn * 64 + np * 16 + hoct + lrow;
        ldsm4(bb[np], Bb + n * 72 + k0 + koct);
      }
#pragma unroll
      for (int mt = 0; mt < 4; mt++) {
#pragma unroll
        for (int np = 0; np < 4; np++) {
          mma_f16(acc[mt][2 * np],     a[mt], bb[np]);
          mma_f16(acc[mt][2 * np + 1], a[mt], bb[np] + 2);
        }
      }
    }
  }

#pragma unroll
  for (int mt = 0; mt < 4; mt++) {
    long row0 = (long)mblk * 128 + wm * 64 + mt * 16 + g;
#pragma unroll
    for (int nt = 0; nt < 8; nt++) {
      int col = nblk * 128 + wn * 64 + nt * 8 + 2 * tg;
      float2 bb = *(const float2*)(bias + col);
      float v00 = (acc[mt][nt][0] + bb.x) * oscale;
      float v01 = (acc[mt][nt][1] + bb.y) * oscale;
      float v10 = (acc[mt][nt][2] + bb.x) * oscale;
      float v11 = (acc[mt][nt][3] + bb.y) * oscale;
      if (OUTH) {
        __half* C = (__half*)Cv;
        int h = col >> 6, d = col & 63;
#pragma unroll
        for (int rr = 0; rr < 2; rr++) {
          long m = row0 + rr * 8;
          int bq = (int)(m >> 12), s = (int)(m & 4095);
          long addr = ((long)(bq * 16 + h) * 4096 + s) * 72 + d;
          *(__half2*)(C + addr) = rr ? __floats2half2_rn(v10, v11)
                                     : __floats2half2_rn(v00, v01);
        }
      } else {
        float* C = (float*)Cv;
        *(float2*)(C + row0 * DM_ + col)       = make_float2(v00, v01);
        *(float2*)(C + (row0 + 8) * DM_ + col) = make_float2(v10, v11);
      }
    }
  }
}

#define QSCALE 0.18033688011112042592f
#define GEMM_SMEM (6 * TILE_B)

__global__ __launch_bounds__(128) void gemm_qkv_kernel(
    const __half* __restrict__ A, const __half* __restrict__ Wqt,
    const __half* __restrict__ Wkt, const __half* __restrict__ Wvt,
    const float* __restrict__ bq, const float* __restrict__ bk,
    const float* __restrict__ bv, __half* __restrict__ Qo,
    __half* __restrict__ Ko, __half* __restrict__ Vo) {
  const __half* Wt = (blockIdx.z == 0) ? Wqt : (blockIdx.z == 1) ? Wkt : Wvt;
  const float* bias = (blockIdx.z == 0) ? bq : (blockIdx.z == 1) ? bk : bv;
  __half* C = (blockIdx.z == 0) ? Qo : (blockIdx.z == 1) ? Ko : Vo;
  float sc = (blockIdx.z == 0) ? QSCALE : 1.0f;
  gemm_body_h<1>(A, Wt, bias, C, sc);
}

__global__ __launch_bounds__(128) void gemm_out_kernel(
    const __half* __restrict__ A, const __half* __restrict__ Wt,
    const float* __restrict__ bias, float* __restrict__ C) {
  gemm_body_h<0>(A, Wt, bias, C, 1.0f);
}

// ---------------------------------------------------------------------------
// Flash attention: CTA = 128 q rows, 4 warps x 32 q rows each. Every K/V
// ldsm fragment is reused across 2 m-tiles -> smem traffic per FLOP halved.
// 3-stage K/V bulk pipeline (stage issued before compute).
// ---------------------------------------------------------------------------
__global__ __launch_bounds__(128) void flash_h_kernel(
    const __half* __restrict__ Qg, const __half* __restrict__ Kg,
    const __half* __restrict__ Vg, __half* __restrict__ attn) {
  __shared__ __align__(16) __half Ks[3][64 * 72];
  __shared__ __align__(16) __half Vs[3][64 * 72];
  __shared__ __align__(8) unsigned long long fmb[3];

  const int tid  = threadIdx.x;
  const int lane = tid & 31;
  const int wid  = tid >> 5;
  const int g    = lane >> 2;
  const int tg   = lane & 3;
  const int lrow = lane & 7;
  const int koct = ((lane >> 3) & 1) << 3;
  const int hoct = (lane >> 4) << 3;
  const int bh   = blockIdx.y;   // b*16 + h
  const int q0   = blockIdx.x * 128;

  const __half* Qb  = Qg + ((long)bh * 4096 + q0) * 72;
  const __half* Kb0 = Kg + (long)bh * 4096 * 72;
  const __half* Vb0 = Vg + (long)bh * 4096 * 72;

  unsigned mbb = (unsigned)__cvta_generic_to_shared(&fmb[0]);
  unsigned ksb = (unsigned)__cvta_generic_to_shared(&Ks[0][0]);
  unsigned vsb = (unsigned)__cvta_generic_to_shared(&Vs[0][0]);

  if (tid == 0) {
#pragma unroll
    for (int i = 0; i < 3; i++) mbar_init(mbb + 8 * i, 1);
  }
  __syncthreads();

  auto stage = [&](int kb) {
    if (tid == 0) {
      int p = kb % 3;
      unsigned mb = mbb + 8 * p;
      mbar_expect(mb, 2 * 9216);
      cpbulk(ksb + p * 9216, Kb0 + (long)(kb * 64) * 72, 9216, mb);
      cpbulk(vsb + p * 9216, Vb0 + (long)(kb * 64) * 72, 9216, mb);
    }
  };

  // Q fragments for 2 m-tiles (32 q rows per warp)
  unsigned qa[2][4][4];
#pragma unroll
  for (int mt = 0; mt < 2; mt++) {
    int qrow = wid * 32 + mt * 16 + g;
#pragma unroll
    for (int ks = 0; ks < 4; ks++) {
      int c = ks * 16 + 2 * tg;
      qa[mt][ks][0] = *(const unsigned*)(Qb + (long)qrow * 72 + c);
      qa[mt][ks][1] = *(const unsigned*)(Qb + (long)(qrow + 8) * 72 + c);
      qa[mt][ks][2] = *(const unsigned*)(Qb + (long)qrow * 72 + c + 8);
      qa[mt][ks][3] = *(const unsigned*)(Qb + (long)(qrow + 8) * 72 + c + 8);
    }
  }

  float oacc[2][8][4];
#pragma unroll
  for (int mt = 0; mt < 2; mt++)
#pragma unroll
    for (int nt = 0; nt < 8; nt++)
#pragma unroll
      for (int j = 0; j < 4; j++) oacc[mt][nt][j] = 0.f;
  float m_r[2][2], l_r[2][2];
#pragma unroll
  for (int mt = 0; mt < 2; mt++) {
    m_r[mt][0] = -INFINITY;
    m_r[mt][1] = -INFINITY;
    l_r[mt][0] = 0.f;
    l_r[mt][1] = 0.f;
  }

  stage(0);
  stage(1);

  for (int kb = 0; kb < S_ / 64; kb++) {
    const int p = kb % 3;
    mbar_wait(mbb + 8 * p, (kb / 3) & 1);
    __syncthreads();
    if (kb + 2 < S_ / 64) stage(kb + 2);

    // ---- S = Q K^T (K frags shared across both m-tiles) ----
    float sacc[2][8][4];
#pragma unroll
    for (int mt = 0; mt < 2; mt++)
#pragma unroll
      for (int nt = 0; nt < 8; nt++)
#pragma unroll
        for (int j = 0; j < 4; j++) sacc[mt][nt][j] = 0.f;
#pragma unroll
    for (int np = 0; np < 4; np++) {
#pragma unroll
      for (int ks = 0; ks < 4; ks++) {
        unsigned bb[4];
        int n = np * 16 + hoct + lrow;
        ldsm4(bb, &Ks[p][n * 72 + ks * 16 + koct]);
#pragma unroll
        for (int mt = 0; mt < 2; mt++) {
          mma_f16(sacc[mt][2 * np],     qa[mt][ks], bb);
          mma_f16(sacc[mt][2 * np + 1], qa[mt][ks], bb + 2);
        }
      }
    }

    // ---- online softmax (per m-tile) + P fragments ----
    unsigned pa[2][4][4];
#pragma unroll
    for (int mt = 0; mt < 2; mt++) {
      float mx0 = -INFINITY, mx1 = -INFINITY;
#pragma unroll
      for (int nt = 0; nt < 8; nt++) {
        mx0 = fmaxf(mx0, fmaxf(sacc[mt][nt][0], sacc[mt][nt][1]));
        mx1 = fmaxf(mx1, fmaxf(sacc[mt][nt][2], sacc[mt][nt][3]));
      }
#pragma unroll
      for (int off = 1; off <= 2; off <<= 1) {
        mx0 = fmaxf(mx0, __shfl_xor_sync(0xffffffffu, mx0, off));
        mx1 = fmaxf(mx1, __shfl_xor_sync(0xffffffffu, mx1, off));
      }
      float mn0 = fmaxf(m_r[mt][0], mx0), mn1 = fmaxf(m_r[mt][1], mx1);
      float al0 = exp2f(m_r[mt][0] - mn0), al1 = exp2f(m_r[mt][1] - mn1);
      m_r[mt][0] = mn0;
      m_r[mt][1] = mn1;

      float ps0 = 0.f, ps1 = 0.f;
#pragma unroll
      for (int nt = 0; nt < 8; nt++) {
        sacc[mt][nt][0] = exp2f(sacc[mt][nt][0] - mn0);
        sacc[mt][nt][1] = exp2f(sacc[mt][nt][1] - mn0);
        sacc[mt][nt][2] = exp2f(sacc[mt][nt][2] - mn1);
        sacc[mt][nt][3] = exp2f(sacc[mt][nt][3] - mn1);
        ps0 += sacc[mt][nt][0] + sacc[mt][nt][1];
        ps1 += sacc[mt][nt][2] + sacc[mt][nt][3];
      }
#pragma unroll
      for (int off = 1; off <= 2; off <<= 1) {
        ps0 += __shfl_xor_sync(0xffffffffu, ps0, off);
        ps1 += __shfl_xor_sync(0xffffffffu, ps1, off);
      }
      l_r[mt][0] = l_r[mt][0] * al0 + ps0;
      l_r[mt][1] = l_r[mt][1] * al1 + ps1;
#pragma unroll
      for (int nt = 0; nt < 8; nt++) {
        oacc[mt][nt][0] *= al0;
        oacc[mt][nt][1] *= al0;
        oacc[mt][nt][2] *= al1;
        oacc[mt][nt][3] *= al1;
      }
#pragma unroll
      for (int ks = 0; ks < 4; ks++) {
        pa[mt][ks][0] = pack_h2(sacc[mt][2 * ks][0],     sacc[mt][2 * ks][1]);
        pa[mt][ks][1] = pack_h2(sacc[mt][2 * ks][2],     sacc[mt][2 * ks][3]);
        pa[mt][ks][2] = pack_h2(sacc[mt][2 * ks + 1][0], sacc[mt][2 * ks + 1][1]);
        pa[mt][ks][3] = pack_h2(sacc[mt][2 * ks + 1][2], sacc[mt][2 * ks + 1][3]);
      }
    }

    // ---- O += P V (V frags shared across both m-tiles) ----
#pragma unroll
    for (int ks = 0; ks < 4; ks++) {
#pragma unroll
      for (int dp = 0; dp < 4; dp++) {
        unsigned vv[4];
        int kv = ks * 16 + koct + lrow;
        int d  = dp * 16 + hoct;
        ldsm4t(vv, &Vs[p][kv * 72 + d]);
#pragma unroll
        for (int mt = 0; mt < 2; mt++) {
          mma_f16(oacc[mt][2 * dp],     pa[mt][ks], vv);
          mma_f16(oacc[mt][2 * dp + 1], pa[mt][ks], vv + 2);
        }
      }
    }
  }

  // epilogue: normalize, write A-packed attn tiles
  const int b = bh >> 4, h = bh & 15;
#pragma unroll
  for (int mt = 0; mt < 2; mt++) {
    float inv0 = 1.f / l_r[mt][0], inv1 = 1.f / l_r[mt][1];
    int row = wid * 32 + mt * 16 + g;
#pragma unroll
    for (int nt = 0; nt < 8; nt++) {
      int col = nt * 8 + 2 * tg;
#pragma unroll
      for (int rr = 0; rr < 2; rr++) {
        int m = b * 4096 + q0 + row + rr * 8;
        long addr = ((long)((m >> 7) * 16 + h)) * TILE_H + (m & 127) * 72 + col;
        *(__half2*)(attn + addr) =
            rr ? __floats2half2_rn(oacc[mt][nt][2] * inv1,
                                   oacc[mt][nt][3] * inv1)
               : __floats2half2_rn(oacc[mt][nt][0] * inv0,
                                   oacc[mt][nt][1] * inv0);
      }
    }
  }
}

// ---------------------------------------------------------------------------
extern "C" void kernel_launch(void* const* d_in, const int* in_sizes, int n_in,
                              void* d_out, int out_size) {
  const float* x  = (const float*)d_in[0];
  const float* Wq = (const float*)d_in[1];
  const float* bq = (const float*)d_in[2];
  const float* Wk = (const float*)d_in[3];
  const float* bk = (const float*)d_in[4];
  const float* Wv = (const float*)d_in[5];
  const float* bv = (const float*)d_in[6];
  const float* Wo = (const float*)d_in[7];
  const float* bo = (const float*)d_in[8];
  float* out = (float*)d_out;

  __half *q, *k, *v, *attn, *xh, *wqt, *wkt, *wvt, *wot;
  cudaGetSymbolAddress((void**)&q, g_q);
  cudaGetSymbolAddress((void**)&k, g_k);
  cudaGetSymbolAddress((void**)&v, g_v);
  cudaGetSymbolAddress((void**)&attn, g_attn);
  cudaGetSymbolAddress((void**)&xh, g_xh);
  cudaGetSymbolAddress((void**)&wqt, g_wqt);
  cudaGetSymbolAddress((void**)&wkt, g_wkt);
  cudaGetSymbolAddress((void**)&wvt, g_wvt);
  cudaGetSymbolAddress((void**)&wot, g_wot);

  f2h_pack<<<MROWS * DM_ / 8 / 256, 256>>>(x, xh);
  dim3 tgrid(DM_ / 32, DM_ / 32, 4);
  f2hT_pack4<<<tgrid, 256>>>(Wq, Wk, Wv, Wo, wqt, wkt, wvt, wot);

  cudaFuncSetAttribute(gemm_qkv_kernel,
                       cudaFuncAttributeMaxDynamicSharedMemorySize, GEMM_SMEM);
  cudaFuncSetAttribute(gemm_out_kernel,
                       cudaFuncAttributeMaxDynamicSharedMemorySize, GEMM_SMEM);

  dim3 qkvgrid(DM_ / 128, MROWS / 128, 3);
  gemm_qkv_kernel<<<qkvgrid, 128, GEMM_SMEM>>>(xh, wqt, wkt, wvt, bq, bk, bv,
                                               q, k, v);

  flash_h_kernel<<<dim3(S_ / 128, B_ * H_), 128>>>(q, k, v, attn);

  dim3 ggrid(DM_ / 128, MROWS / 128);
  gemm_out_kernel<<<ggrid, 128, GEMM_SMEM>>>(attn, wot, bo, out);
}